// round 13
// baseline (speedup 1.0000x reference)
#include <cuda_runtime.h>
#include <math.h>

// AFM layer: B=2048, F=50, E=64, A=10, P=1225.
// out[b] = sum_p softmax(l)_p * q_p.
// Each block handles TWO batch elements (grid = B/2); the second element's x
// tile is prefetched into registers during the first element's compute, so its
// DRAM latency is hidden. 352 threads; each thread owns a 2x2 (i,j) Gram tile.
// f32x2 packed FMA; q packed 2-pairs/reg (p_e duplicated in W cols 10,11).

#define NF 50
#define NE 64
#define NA 10
#define WC 12               // cols: 0-9 = W, 10 = p, 11 = p
#define NPAIR 1225
#define NTILE 325
#define THREADS 352
#define EPITCH 68           // dwords; conflict-free LDS.128
#define ZROW 25
#define NSTAGE 10           // ceil(3200/352)

typedef unsigned long long u64;

__device__ unsigned int g_tile[THREADS];   // mask(4)<<28 | (bi*EPITCH)<<14 | (bj*EPITCH)

__global__ void init_tiles_kernel() {
    int s = blockIdx.x * blockDim.x + threadIdx.x;
    if (s >= THREADS) return;
    unsigned v;
    if (s < NTILE) {
        int rem = s, bi = 0;
        while (rem >= 25 - bi) { rem -= 25 - bi; ++bi; }
        int bj = bi + rem;
        unsigned mask = (bi < bj) ? 0xFu : 0x2u;   // diag: only (2bi, 2bj+1)
        v = (mask << 28) | ((unsigned)(bi * EPITCH) << 14) | (unsigned)(bj * EPITCH);
    } else {
        v = ((unsigned)(ZROW * EPITCH) << 14) | (unsigned)(ZROW * EPITCH);
    }
    g_tile[s] = v;
}

__device__ __forceinline__ u64 f2_mul(u64 a, u64 b) {
    u64 d; asm("mul.rn.f32x2 %0, %1, %2;" : "=l"(d) : "l"(a), "l"(b)); return d;
}
__device__ __forceinline__ u64 f2_fma(u64 a, u64 b, u64 c) {
    u64 d; asm("fma.rn.f32x2 %0, %1, %2, %3;" : "=l"(d) : "l"(a), "l"(b), "l"(c)); return d;
}
__device__ __forceinline__ u64 f2_pack(float lo, float hi) {
    u64 d; asm("mov.b64 %0, {%1, %2};" : "=l"(d) : "f"(lo), "f"(hi)); return d;
}
__device__ __forceinline__ u64 f2_bcast(float v) {
    u64 d; asm("mov.b64 %0, {%1, %1};" : "=l"(d) : "f"(v)); return d;
}
__device__ __forceinline__ void f2_unpack(u64 v, float& lo, float& hi) {
    asm("mov.b64 {%0, %1}, %2;" : "=f"(lo), "=f"(hi) : "l"(v));
}

// Full per-element compute: Gram-tile accumulation + softmax reduction + store.
__device__ __forceinline__ void compute_elem(
    const float* __restrict__ xev, const float* __restrict__ xod,
    const float* __restrict__ Ws,
    const float* __restrict__ bs, const float* __restrict__ hs,
    float* red, float* red2, float* bcastp,
    unsigned tv, int tid, int lane, int wid,
    float* __restrict__ outp)
{
    const int bio  = (int)((tv >> 14) & 0x3FFFu);
    const int bjo  = (int)(tv & 0x3FFFu);
    const int mask = (int)(tv >> 28);

    u64 acc[4][5];
#pragma unroll
    for (int p = 0; p < 4; ++p)
#pragma unroll
        for (int k = 0; k < 5; ++k) acc[p][k] = 0ull;
    u64 qacc01 = 0ull, qacc23 = 0ull;

#pragma unroll 1
    for (int ec = 0; ec < NE; ec += 4) {
        ulonglong2 Xie = *reinterpret_cast<const ulonglong2*>(xev + bio + ec);
        ulonglong2 Xio = *reinterpret_cast<const ulonglong2*>(xod + bio + ec);
        ulonglong2 Xje = *reinterpret_cast<const ulonglong2*>(xev + bjo + ec);
        ulonglong2 Xjo = *reinterpret_cast<const ulonglong2*>(xod + bjo + ec);
        float ie[4], io[4], je[4], jo[4];
        f2_unpack(Xie.x, ie[0], ie[1]); f2_unpack(Xie.y, ie[2], ie[3]);
        f2_unpack(Xio.x, io[0], io[1]); f2_unpack(Xio.y, io[2], io[3]);
        f2_unpack(Xje.x, je[0], je[1]); f2_unpack(Xje.y, je[2], je[3]);
        f2_unpack(Xjo.x, jo[0], jo[1]); f2_unpack(Xjo.y, jo[2], jo[3]);

#pragma unroll
        for (int h = 0; h < 4; ++h) {
            const ulonglong2* wr =
                reinterpret_cast<const ulonglong2*>(Ws + (ec + h) * WC);
            ulonglong2 wa = wr[0], wb = wr[1], wc = wr[2];
            u64 w0 = wa.x, w1 = wa.y, w2 = wb.x, w3 = wb.y, w4 = wc.x;
            u64 wq = wc.y;                          // (p_e, p_e)

            u64 jp  = f2_pack(je[h], jo[h]);
            u64 m01 = f2_mul(f2_bcast(ie[h]), jp);  // (pr_p0, pr_p1)
            u64 m23 = f2_mul(f2_bcast(io[h]), jp);  // (pr_p2, pr_p3)

            qacc01 = f2_fma(m01, wq, qacc01);
            qacc23 = f2_fma(m23, wq, qacc23);

            float p0, p1, p2, p3;
            f2_unpack(m01, p0, p1);
            f2_unpack(m23, p2, p3);
            u64 br0 = f2_bcast(p0), br1 = f2_bcast(p1);
            u64 br2 = f2_bcast(p2), br3 = f2_bcast(p3);

            acc[0][0] = f2_fma(br0, w0, acc[0][0]);
            acc[0][1] = f2_fma(br0, w1, acc[0][1]);
            acc[0][2] = f2_fma(br0, w2, acc[0][2]);
            acc[0][3] = f2_fma(br0, w3, acc[0][3]);
            acc[0][4] = f2_fma(br0, w4, acc[0][4]);
            acc[1][0] = f2_fma(br1, w0, acc[1][0]);
            acc[1][1] = f2_fma(br1, w1, acc[1][1]);
            acc[1][2] = f2_fma(br1, w2, acc[1][2]);
            acc[1][3] = f2_fma(br1, w3, acc[1][3]);
            acc[1][4] = f2_fma(br1, w4, acc[1][4]);
            acc[2][0] = f2_fma(br2, w0, acc[2][0]);
            acc[2][1] = f2_fma(br2, w1, acc[2][1]);
            acc[2][2] = f2_fma(br2, w2, acc[2][2]);
            acc[2][3] = f2_fma(br2, w3, acc[2][3]);
            acc[2][4] = f2_fma(br2, w4, acc[2][4]);
            acc[3][0] = f2_fma(br3, w0, acc[3][0]);
            acc[3][1] = f2_fma(br3, w1, acc[3][1]);
            acc[3][2] = f2_fma(br3, w2, acc[3][2]);
            acc[3][3] = f2_fma(br3, w3, acc[3][3]);
            acc[3][4] = f2_fma(br3, w4, acc[3][4]);
        }
    }

    float qsc[4];
    f2_unpack(qacc01, qsc[0], qsc[1]);
    f2_unpack(qacc23, qsc[2], qsc[3]);

    float logit[4];
#pragma unroll
    for (int p = 0; p < 4; ++p) {
        float l = 0.0f;
#pragma unroll
        for (int k = 0; k < 5; ++k) {
            float a0, a1;
            f2_unpack(acc[p][k], a0, a1);
            a0 += bs[2 * k];
            a1 += bs[2 * k + 1];
            a0 = a0 > 0.0f ? a0 : 0.0f;
            a1 = a1 > 0.0f ? a1 : 0.0f;
            l = fmaf(hs[2 * k], a0, l);
            l = fmaf(hs[2 * k + 1], a1, l);
        }
        logit[p] = (mask >> p) & 1 ? l : -INFINITY;
    }

    // guard: previous element's epilogue reads of red[] must be done
    __syncthreads();

    float m = fmaxf(fmaxf(logit[0], logit[1]), fmaxf(logit[2], logit[3]));
#pragma unroll
    for (int o = 16; o > 0; o >>= 1)
        m = fmaxf(m, __shfl_xor_sync(0xFFFFFFFFu, m, o));
    if (lane == 0) red[wid] = m;
    __syncthreads();
    if (tid == 0) {
        float mm = red[0];
#pragma unroll
        for (int w = 1; w < THREADS / 32; ++w) mm = fmaxf(mm, red[w]);
        *bcastp = mm;
    }
    __syncthreads();
    const float mAll = *bcastp;

    float s = 0.0f, sq = 0.0f;
#pragma unroll
    for (int p = 0; p < 4; ++p) {
        float e = expf(logit[p] - mAll);
        s += e;
        sq = fmaf(e, qsc[p], sq);
    }
#pragma unroll
    for (int o = 16; o > 0; o >>= 1) {
        s  += __shfl_xor_sync(0xFFFFFFFFu, s, o);
        sq += __shfl_xor_sync(0xFFFFFFFFu, sq, o);
    }
    if (lane == 0) { red[wid] = s; red2[wid] = sq; }
    __syncthreads();
    if (tid == 0) {
        float ss = 0.0f, ssq = 0.0f;
#pragma unroll
        for (int w = 0; w < THREADS / 32; ++w) { ss += red[w]; ssq += red2[w]; }
        *outp = ssq / ss;
    }
}

__global__ __launch_bounds__(THREADS, 2)
void afm_kernel(const float* __restrict__ x,
                const float* __restrict__ W,
                const float* __restrict__ bvec,
                const float* __restrict__ hvec,
                const float* __restrict__ pvec,
                float* __restrict__ out, int B)
{
    __shared__ __align__(16) float xev0[(ZROW + 1) * EPITCH];
    __shared__ __align__(16) float xod0[(ZROW + 1) * EPITCH];
    __shared__ __align__(16) float xev1[(ZROW + 1) * EPITCH];
    __shared__ __align__(16) float xod1[(ZROW + 1) * EPITCH];
    __shared__ __align__(16) float Ws[NE * WC];
    __shared__ float bs[NA];
    __shared__ float hs[NA];
    __shared__ float red[11];
    __shared__ float red2[11];
    __shared__ float bcast;

    const int tid  = threadIdx.x;
    const int lane = tid & 31;
    const int wid  = tid >> 5;
    const int b0   = blockIdx.x * 2;
    const int b1   = b0 + 1;

    // ---- element 0 x tile -> smem ----
    const float* xb0 = x + (size_t)b0 * (NF * NE);
    for (int idx = tid; idx < NF * NE; idx += THREADS) {
        int r = idx >> 6;
        int c = idx & 63;
        float v = xb0[idx];
        if (r & 1) xod0[(r >> 1) * EPITCH + c] = v;
        else       xev0[(r >> 1) * EPITCH + c] = v;
    }
    for (int c = tid; c < EPITCH; c += THREADS) {
        xev0[ZROW * EPITCH + c] = 0.0f;
        xod0[ZROW * EPITCH + c] = 0.0f;
        xev1[ZROW * EPITCH + c] = 0.0f;
        xod1[ZROW * EPITCH + c] = 0.0f;
    }
    for (int idx = tid; idx < NE * WC; idx += THREADS) {
        int e = idx / WC;
        int c = idx - e * WC;
        float v;
        if (c < NA) v = W[e * NA + c];
        else        v = pvec[e];          // cols 10 & 11 = p_e
        Ws[idx] = v;
    }
    if (tid < NA) { bs[tid] = bvec[tid]; hs[tid] = hvec[tid]; }
    const unsigned tv = g_tile[tid];

    // ---- prefetch element 1 x tile into registers (latency hidden by elem0) ----
    float stage[NSTAGE];
    const bool have1 = (b1 < B);
    const float* xb1 = x + (size_t)(have1 ? b1 : b0) * (NF * NE);
#pragma unroll
    for (int k = 0; k < NSTAGE; ++k) {
        int idx = tid + k * THREADS;
        stage[k] = (idx < NF * NE) ? xb1[idx] : 0.0f;
    }

    __syncthreads();

    // ---- element 0 compute + reduce + store ----
    compute_elem(xev0, xod0, Ws, bs, hs, red, red2, &bcast,
                 tv, tid, lane, wid, out + b0);

    // ---- commit element 1 tile, then compute ----
#pragma unroll
    for (int k = 0; k < NSTAGE; ++k) {
        int idx = tid + k * THREADS;
        if (idx < NF * NE) {
            int r = idx >> 6;
            int c = idx & 63;
            if (r & 1) xod1[(r >> 1) * EPITCH + c] = stage[k];
            else       xev1[(r >> 1) * EPITCH + c] = stage[k];
        }
    }
    __syncthreads();

    if (have1)
        compute_elem(xev1, xod1, Ws, bs, hs, red, red2, &bcast,
                     tv, tid, lane, wid, out + b1);
}

extern "C" void kernel_launch(void* const* d_in, const int* in_sizes, int n_in,
                              void* d_out, int out_size)
{
    const float* x = (const float*)d_in[0];   // [B, 50, 64]
    const float* W = (const float*)d_in[1];   // [64, 10]
    const float* b = (const float*)d_in[2];   // [10]
    const float* h = (const float*)d_in[3];   // [10, 1]
    const float* p = (const float*)d_in[4];   // [64, 1]
    float* out = (float*)d_out;               // [B, 1]

    int B = in_sizes[0] / (NF * NE);
    init_tiles_kernel<<<1, THREADS>>>();
    afm_kernel<<<(B + 1) / 2, THREADS>>>(x, W, b, h, p, out, B);
}

// round 14
// speedup vs baseline: 1.1989x; 1.1989x over previous
#include <cuda_runtime.h>
#include <math.h>

// AFM layer: B=2048, F=50, E=64, A=10, P=1225.
// out[b] = sum_p softmax(l)_p * q_p.
// One block per batch element; 352 threads; each thread owns a 2x2 (i,j) Gram
// tile (4 pairs). f32x2 packed FMA. Weights/bias/h/p live in __constant__
// memory (separate const port) so the shared-memory/LSU path carries ONLY the
// x-tile loads (4 LDS.128 per thread per 4e-chunk).

#define NF 50
#define NE 64
#define NA 10
#define NPAIR 1225
#define NTILE 325
#define THREADS 352
#define EPITCH 68           // dwords; conflict-free LDS.128
#define ZROW 25

typedef unsigned long long u64;

__constant__ float cW[NE * NA];   // raw [64,10] row-major
__constant__ float cB[NA];
__constant__ float cH[NA];
__constant__ float cP[NE];

__device__ unsigned int g_tile[THREADS];   // mask(4)<<28 | (bi*EPITCH)<<14 | (bj*EPITCH)

__global__ void init_tiles_kernel() {
    int s = blockIdx.x * blockDim.x + threadIdx.x;
    if (s >= THREADS) return;
    unsigned v;
    if (s < NTILE) {
        int rem = s, bi = 0;
        while (rem >= 25 - bi) { rem -= 25 - bi; ++bi; }
        int bj = bi + rem;
        unsigned mask = (bi < bj) ? 0xFu : 0x2u;   // diag: only (2bi, 2bj+1)
        v = (mask << 28) | ((unsigned)(bi * EPITCH) << 14) | (unsigned)(bj * EPITCH);
    } else {
        v = ((unsigned)(ZROW * EPITCH) << 14) | (unsigned)(ZROW * EPITCH);
    }
    g_tile[s] = v;
}

__device__ __forceinline__ u64 f2_mul(u64 a, u64 b) {
    u64 d; asm("mul.rn.f32x2 %0, %1, %2;" : "=l"(d) : "l"(a), "l"(b)); return d;
}
__device__ __forceinline__ u64 f2_fma(u64 a, u64 b, u64 c) {
    u64 d; asm("fma.rn.f32x2 %0, %1, %2, %3;" : "=l"(d) : "l"(a), "l"(b), "l"(c)); return d;
}
__device__ __forceinline__ u64 f2_pack(float lo, float hi) {
    u64 d; asm("mov.b64 %0, {%1, %2};" : "=l"(d) : "f"(lo), "f"(hi)); return d;
}
__device__ __forceinline__ u64 f2_bcast(float v) {
    u64 d; asm("mov.b64 %0, {%1, %1};" : "=l"(d) : "f"(v)); return d;
}
__device__ __forceinline__ void f2_unpack(u64 v, float& lo, float& hi) {
    asm("mov.b64 {%0, %1}, %2;" : "=f"(lo), "=f"(hi) : "l"(v));
}

__global__ __launch_bounds__(THREADS, 2)
void afm_kernel(const float* __restrict__ x, float* __restrict__ out)
{
    __shared__ __align__(16) float xev[(ZROW + 1) * EPITCH];
    __shared__ __align__(16) float xod[(ZROW + 1) * EPITCH];
    __shared__ float red[11];
    __shared__ float red2[11];
    __shared__ float bcast;

    const int tid  = threadIdx.x;
    const int lane = tid & 31;
    const int wid  = tid >> 5;
    const int b    = blockIdx.x;

    // ---- load x[b] split into even/odd row arrays ----
    const float* xb = x + (size_t)b * (NF * NE);
    for (int idx = tid; idx < NF * NE; idx += THREADS) {
        int r = idx >> 6;
        int c = idx & 63;
        float v = xb[idx];
        if (r & 1) xod[(r >> 1) * EPITCH + c] = v;
        else       xev[(r >> 1) * EPITCH + c] = v;
    }
    for (int c = tid; c < EPITCH; c += THREADS) {
        xev[ZROW * EPITCH + c] = 0.0f;
        xod[ZROW * EPITCH + c] = 0.0f;
    }
    const unsigned tv = g_tile[tid];
    __syncthreads();

    const int bio  = (int)((tv >> 14) & 0x3FFFu);
    const int bjo  = (int)(tv & 0x3FFFu);
    const int mask = (int)(tv >> 28);

    // pairs: 0=(ie,je) 1=(ie,jo) 2=(io,je) 3=(io,jo); acc lanes = W cols (2k,2k+1)
    u64 acc[4][5];
#pragma unroll
    for (int p = 0; p < 4; ++p)
#pragma unroll
        for (int k = 0; k < 5; ++k) acc[p][k] = 0ull;
    u64 qacc01 = 0ull, qacc23 = 0ull;   // lanes (q_p0,q_p1), (q_p2,q_p3)

#pragma unroll 1
    for (int ec = 0; ec < NE; ec += 4) {
        ulonglong2 Xie = *reinterpret_cast<const ulonglong2*>(xev + bio + ec);
        ulonglong2 Xio = *reinterpret_cast<const ulonglong2*>(xod + bio + ec);
        ulonglong2 Xje = *reinterpret_cast<const ulonglong2*>(xev + bjo + ec);
        ulonglong2 Xjo = *reinterpret_cast<const ulonglong2*>(xod + bjo + ec);
        float ie[4], io[4], je[4], jo[4];
        f2_unpack(Xie.x, ie[0], ie[1]); f2_unpack(Xie.y, ie[2], ie[3]);
        f2_unpack(Xio.x, io[0], io[1]); f2_unpack(Xio.y, io[2], io[3]);
        f2_unpack(Xje.x, je[0], je[1]); f2_unpack(Xje.y, je[2], je[3]);
        f2_unpack(Xjo.x, jo[0], jo[1]); f2_unpack(Xjo.y, jo[2], jo[3]);

#pragma unroll
        for (int h = 0; h < 4; ++h) {
            // weight pairs from the constant port (uniform addresses)
            const float* wr = cW + (ec + h) * NA;
            u64 w0 = *reinterpret_cast<const u64*>(wr + 0);   // (w_c0, w_c1)
            u64 w1 = *reinterpret_cast<const u64*>(wr + 2);
            u64 w2 = *reinterpret_cast<const u64*>(wr + 4);
            u64 w3 = *reinterpret_cast<const u64*>(wr + 6);
            u64 w4 = *reinterpret_cast<const u64*>(wr + 8);
            u64 wq = f2_bcast(cP[ec + h]);                    // (p_e, p_e)

            u64 jp  = f2_pack(je[h], jo[h]);
            u64 m01 = f2_mul(f2_bcast(ie[h]), jp);  // (pr_p0, pr_p1)
            u64 m23 = f2_mul(f2_bcast(io[h]), jp);  // (pr_p2, pr_p3)

            qacc01 = f2_fma(m01, wq, qacc01);
            qacc23 = f2_fma(m23, wq, qacc23);

            float p0, p1, p2, p3;
            f2_unpack(m01, p0, p1);
            f2_unpack(m23, p2, p3);
            u64 br0 = f2_bcast(p0), br1 = f2_bcast(p1);
            u64 br2 = f2_bcast(p2), br3 = f2_bcast(p3);

            acc[0][0] = f2_fma(br0, w0, acc[0][0]);
            acc[0][1] = f2_fma(br0, w1, acc[0][1]);
            acc[0][2] = f2_fma(br0, w2, acc[0][2]);
            acc[0][3] = f2_fma(br0, w3, acc[0][3]);
            acc[0][4] = f2_fma(br0, w4, acc[0][4]);
            acc[1][0] = f2_fma(br1, w0, acc[1][0]);
            acc[1][1] = f2_fma(br1, w1, acc[1][1]);
            acc[1][2] = f2_fma(br1, w2, acc[1][2]);
            acc[1][3] = f2_fma(br1, w3, acc[1][3]);
            acc[1][4] = f2_fma(br1, w4, acc[1][4]);
            acc[2][0] = f2_fma(br2, w0, acc[2][0]);
            acc[2][1] = f2_fma(br2, w1, acc[2][1]);
            acc[2][2] = f2_fma(br2, w2, acc[2][2]);
            acc[2][3] = f2_fma(br2, w3, acc[2][3]);
            acc[2][4] = f2_fma(br2, w4, acc[2][4]);
            acc[3][0] = f2_fma(br3, w0, acc[3][0]);
            acc[3][1] = f2_fma(br3, w1, acc[3][1]);
            acc[3][2] = f2_fma(br3, w2, acc[3][2]);
            acc[3][3] = f2_fma(br3, w3, acc[3][3]);
            acc[3][4] = f2_fma(br3, w4, acc[3][4]);
        }
    }

    // ---- logits + q ----
    float qsc[4];
    f2_unpack(qacc01, qsc[0], qsc[1]);
    f2_unpack(qacc23, qsc[2], qsc[3]);

    float logit[4];
#pragma unroll
    for (int p = 0; p < 4; ++p) {
        float l = 0.0f;
#pragma unroll
        for (int k = 0; k < 5; ++k) {
            float a0, a1;
            f2_unpack(acc[p][k], a0, a1);
            a0 += cB[2 * k];
            a1 += cB[2 * k + 1];
            a0 = a0 > 0.0f ? a0 : 0.0f;
            a1 = a1 > 0.0f ? a1 : 0.0f;
            l = fmaf(cH[2 * k], a0, l);
            l = fmaf(cH[2 * k + 1], a1, l);
        }
        logit[p] = (mask >> p) & 1 ? l : -INFINITY;
    }

    // ---- softmax-weighted scalar reduction ----
    float m = fmaxf(fmaxf(logit[0], logit[1]), fmaxf(logit[2], logit[3]));
#pragma unroll
    for (int o = 16; o > 0; o >>= 1)
        m = fmaxf(m, __shfl_xor_sync(0xFFFFFFFFu, m, o));
    if (lane == 0) red[wid] = m;
    __syncthreads();
    if (tid == 0) {
        float mm = red[0];
#pragma unroll
        for (int w = 1; w < THREADS / 32; ++w) mm = fmaxf(mm, red[w]);
        bcast = mm;
    }
    __syncthreads();
    const float mAll = bcast;

    float s = 0.0f, sq = 0.0f;
#pragma unroll
    for (int p = 0; p < 4; ++p) {
        float e = expf(logit[p] - mAll);
        s += e;
        sq = fmaf(e, qsc[p], sq);
    }
#pragma unroll
    for (int o = 16; o > 0; o >>= 1) {
        s  += __shfl_xor_sync(0xFFFFFFFFu, s, o);
        sq += __shfl_xor_sync(0xFFFFFFFFu, sq, o);
    }
    if (lane == 0) { red[wid] = s; red2[wid] = sq; }
    __syncthreads();
    if (tid == 0) {
        float ss = 0.0f, ssq = 0.0f;
#pragma unroll
        for (int w = 0; w < THREADS / 32; ++w) { ss += red[w]; ssq += red2[w]; }
        out[b] = ssq / ss;
    }
}

extern "C" void kernel_launch(void* const* d_in, const int* in_sizes, int n_in,
                              void* d_out, int out_size)
{
    const float* x = (const float*)d_in[0];   // [B, 50, 64]
    float* out = (float*)d_out;               // [B, 1]

    // Stage grid-invariant params into constant memory (D2D async copies are
    // graph-capturable memcpy nodes on the same stream as the kernels).
    cudaMemcpyToSymbolAsync(cW, d_in[1], NE * NA * sizeof(float), 0,
                            cudaMemcpyDeviceToDevice, 0);
    cudaMemcpyToSymbolAsync(cB, d_in[2], NA * sizeof(float), 0,
                            cudaMemcpyDeviceToDevice, 0);
    cudaMemcpyToSymbolAsync(cH, d_in[3], NA * sizeof(float), 0,
                            cudaMemcpyDeviceToDevice, 0);
    cudaMemcpyToSymbolAsync(cP, d_in[4], NE * sizeof(float), 0,
                            cudaMemcpyDeviceToDevice, 0);

    int B = in_sizes[0] / (NF * NE);
    init_tiles_kernel<<<1, THREADS>>>();
    afm_kernel<<<B, THREADS>>>(x, out);
}